// round 16
// baseline (speedup 1.0000x reference)
#include <cuda_runtime.h>

// out[b,u] = prod_f(in[b,f]*w[f,u]) + bias[u] = P[b]*W[u] + bias[u]
// B=32768, F=32, U=256.
static constexpr int Bn = 32768;
static constexpr int Fn = 32;
static constexpr int Un = 256;

static constexpr int THREADS       = 256;               // 8 warps
static constexpr int ROWS_PER_WARP = 8;                 // 2 independent LDG.128/lane
static constexpr int ROWS_PER_BLK  = ROWS_PER_WARP * 8; // 64
static constexpr int GRID          = Bn / ROWS_PER_BLK; // 512 -> one wave

// 256-bit global store (sm_100a+/PTX 8.8): one row slice (8 fp32) per lane,
// 1024B contiguous per warp-instruction. Halves store instruction count vs STG.128.
__device__ __forceinline__ void stg256(float* p,
                                       float a0, float a1, float a2, float a3,
                                       float a4, float a5, float a6, float a7) {
    asm volatile(
        "st.global.v8.f32 [%0], {%1, %2, %3, %4, %5, %6, %7, %8};"
        :: "l"(p), "f"(a0), "f"(a1), "f"(a2), "f"(a3),
                   "f"(a4), "f"(a5), "f"(a6), "f"(a7)
        : "memory");
}

// One wave, everything resident, MLP=2 input loads, STG.256 epilogue.
__global__ __launch_bounds__(THREADS)
void fused_kernel(const float* __restrict__ in,
                  const float* __restrict__ w,
                  const float* __restrict__ bias,
                  float* __restrict__ out) {
    __shared__ float sW[Un];

    const int t    = threadIdx.x;
    const int lane = t & 31;
    const int warp = t >> 5;

    // ---- issue BOTH input loads first: 8 rows * 32 f = 64 float4 ----
    const long long rowbase = (long long)blockIdx.x * ROWS_PER_BLK
                            + (long long)warp * ROWS_PER_WARP;
    const float4* in4 = reinterpret_cast<const float4*>(in + rowbase * Fn);
    const float4 v0 = in4[lane];          // rows rowbase..+3, lane l -> row l>>3
    const float4 v1 = in4[lane + 32];     // rows rowbase+4..+7

    // ---- one-time W phase: thread t owns column t (R13-proven scalar form) ----
    {
        float q0 = 1.0f, q1 = 1.0f, q2 = 1.0f, q3 = 1.0f;
#pragma unroll
        for (int f = 0; f < Fn; f += 4) {
            q0 *= w[(f + 0) * Un + t];
            q1 *= w[(f + 1) * Un + t];
            q2 *= w[(f + 2) * Un + t];
            q3 *= w[(f + 3) * Un + t];
        }
        sW[t] = (q0 * q1) * (q2 * q3);
    }

    // bias -> regs: lane owns contiguous columns [8*lane, 8*lane+8)
    const float4* B4 = reinterpret_cast<const float4*>(bias);
    const float4 bv0 = B4[2 * lane];
    const float4 bv1 = B4[2 * lane + 1];

    __syncthreads();

    // W -> regs, same contiguous ownership (2-way smem access, broadcast-free)
    const float4* sW4 = reinterpret_cast<const float4*>(sW);
    const float4 wv0 = sW4[2 * lane];
    const float4 wv1 = sW4[2 * lane + 1];

    // ---- two interleaved row-product reductions (independent chains) ----
    float p0 = v0.x * v0.y * v0.z * v0.w;
    float p1 = v1.x * v1.y * v1.z * v1.w;
    p0 *= __shfl_xor_sync(0xffffffffu, p0, 1);
    p1 *= __shfl_xor_sync(0xffffffffu, p1, 1);
    p0 *= __shfl_xor_sync(0xffffffffu, p0, 2);
    p1 *= __shfl_xor_sync(0xffffffffu, p1, 2);
    p0 *= __shfl_xor_sync(0xffffffffu, p0, 4);
    p1 *= __shfl_xor_sync(0xffffffffu, p1, 4);
    // lanes 8r..8r+7: p0 = product of row (rowbase+r), p1 = row (rowbase+4+r)

    // ---- 8 coalesced STG.256 per warp (1 per row), all independent ----
    float* orow = out + rowbase * Un + lane * 8;   // lane's 32B slice of each row
#pragma unroll
    for (int r = 0; r < 4; ++r) {
        const float pa = __shfl_sync(0xffffffffu, p0, r * 8);
        const float pb = __shfl_sync(0xffffffffu, p1, r * 8);
        stg256(orow + (long long)r * Un,
               fmaf(pa, wv0.x, bv0.x), fmaf(pa, wv0.y, bv0.y),
               fmaf(pa, wv0.z, bv0.z), fmaf(pa, wv0.w, bv0.w),
               fmaf(pa, wv1.x, bv1.x), fmaf(pa, wv1.y, bv1.y),
               fmaf(pa, wv1.z, bv1.z), fmaf(pa, wv1.w, bv1.w));
        stg256(orow + (long long)(r + 4) * Un,
               fmaf(pb, wv0.x, bv0.x), fmaf(pb, wv0.y, bv0.y),
               fmaf(pb, wv0.z, bv0.z), fmaf(pb, wv0.w, bv0.w),
               fmaf(pb, wv1.x, bv1.x), fmaf(pb, wv1.y, bv1.y),
               fmaf(pb, wv1.z, bv1.z), fmaf(pb, wv1.w, bv1.w));
    }
}

extern "C" void kernel_launch(void* const* d_in, const int* in_sizes, int n_in,
                              void* d_out, int out_size) {
    // metadata order: inputs [B,F], weight [F,U], weight_selector [F,U] (dead), bias [U]
    const float* in   = (const float*)d_in[0];
    const float* w    = (const float*)d_in[1];
    const float* bias = (const float*)d_in[3];
    float* out        = (float*)d_out;

    fused_kernel<<<GRID, THREADS>>>(in, w, bias, out);
}